// round 11
// baseline (speedup 1.0000x reference)
#include <cuda_runtime.h>
#include <cuda_bf16.h>

// Problem constants
#define A_N 2048
#define D_N 64
#define F_N 12
#define K_N (A_N * F_N)   // 24576
#define C_N 66            // D + 2
#define GN  (F_N * D_N)   // 768

// Split-K for the tensor GEMM: 16 M-tiles x 9 K-splits = 144 CTAs (one wave)
#define NSPLIT 9
#define KT_TOTAL 768          // 24576 / 32 K-tiles (BK=32)
#define KT_PER   86           // splits 0..7: 86 tiles, split 8: 80

// mma_gemm smem: A = 2 stages x 20480B, B = 3 stages x 10240B
// (rows padded to 80B for conflict-free ldmatrix)
#define A_ST_SZ 20480
#define A_AH    0
#define A_AL    10240
#define B_BASE  (2 * A_ST_SZ)        // 40960
#define B_ST_SZ 10240
#define B_BH    0
#define B_BL    5120
#define TC_SMEM (B_BASE + 3 * B_ST_SZ)   // 71680

// ---------------------------------------------------------------------------
// Scratch (device globals only — no allocation allowed)
// ---------------------------------------------------------------------------
__device__ __nv_bfloat16 g_wth[(size_t)D_N * K_N];  // Wt hi: [o][k] K-major
__device__ __nv_bfloat16 g_wtl[(size_t)D_N * K_N];  // Wt lo: [o][k]
__device__ float g_G[2][D_N * GN];
__device__ float g_bt[2][A_N * D_N];
__device__ float g_W[K_N * D_N];                    // W[k][o] fp32 (wgemm out)
__device__ float g_xa[A_N * D_N];
__device__ float g_xb[A_N * D_N];
__device__ float g_part[NSPLIT][A_N * D_N];

// ---------------------------------------------------------------------------
// PTX helpers (all baseline sm_80-era: no arch-suffix-gated features)
// ---------------------------------------------------------------------------
__device__ __forceinline__ unsigned smem_u32(const void* p) {
    unsigned a;
    asm("{ .reg .u64 t; cvta.to.shared.u64 t, %1; cvt.u32.u64 %0, t; }"
        : "=r"(a) : "l"(p));
    return a;
}
__device__ __forceinline__ void cpasync16(unsigned dst, const void* src) {
    asm volatile("cp.async.cg.shared.global [%0], [%1], 16;"
                 :: "r"(dst), "l"(src) : "memory");
}
__device__ __forceinline__ void cp_commit() {
    asm volatile("cp.async.commit_group;" ::: "memory");
}
template <int N>
__device__ __forceinline__ void cp_wait() {
    asm volatile("cp.async.wait_group %0;" :: "n"(N) : "memory");
}
__device__ __forceinline__ void ldmx4(unsigned r[4], unsigned addr) {
    asm volatile("ldmatrix.sync.aligned.m8n8.x4.shared.b16 {%0,%1,%2,%3}, [%4];"
                 : "=r"(r[0]), "=r"(r[1]), "=r"(r[2]), "=r"(r[3]) : "r"(addr));
}
__device__ __forceinline__ void hmma(float c[4], const unsigned a[4],
                                     unsigned b0, unsigned b1) {
    asm volatile(
        "mma.sync.aligned.m16n8k16.row.col.f32.bf16.bf16.f32 "
        "{%0,%1,%2,%3}, {%4,%5,%6,%7}, {%8,%9}, {%0,%1,%2,%3};"
        : "+f"(c[0]), "+f"(c[1]), "+f"(c[2]), "+f"(c[3])
        : "r"(a[0]), "r"(a[1]), "r"(a[2]), "r"(a[3]), "r"(b0), "r"(b1));
}
__device__ __forceinline__ void split_bf16(float x, __nv_bfloat16& h, __nv_bfloat16& l) {
    h = __float2bfloat16_rn(x);
    l = __float2bfloat16_rn(x - __bfloat162float(h));
}

// ---------------------------------------------------------------------------
// Prep: transpose filters into G
// ---------------------------------------------------------------------------
__global__ void prep_g_kernel(const float* __restrict__ f0, const float* __restrict__ f1) {
    int i = blockIdx.x * blockDim.x + threadIdx.x;
    if (i >= 2 * D_N * GN) return;
    int fi = i / (D_N * GN);
    int r  = i % (D_N * GN);
    int d  = r / GN;
    int j  = r % GN;
    int f  = j >> 6;
    int o  = j & 63;
    const float* filt = fi ? f1 : f0;
    g_G[fi][r] = filt[(o * F_N + f) * C_N + d];
}

// Prep: bond term (x-independent)
__global__ void prep_bt_kernel(const float* __restrict__ bond,
                               const float* __restrict__ f0,
                               const float* __restrict__ f1) {
    int i = blockIdx.x * blockDim.x + threadIdx.x;
    if (i >= 2 * A_N * D_N) return;
    int fi = i / (A_N * D_N);
    int r  = i % (A_N * D_N);
    int a  = r / D_N;
    int o  = r % D_N;
    const float* filt = fi ? f1 : f0;
    float s = 0.f;
#pragma unroll
    for (int f = 0; f < F_N; ++f) {
        s += bond[(a * F_N + f) * 2 + 0] * filt[(o * F_N + f) * C_N + 64];
        s += bond[(a * F_N + f) * 2 + 1] * filt[(o * F_N + f) * C_N + 65];
    }
    g_bt[fi][r] = s;
}

// ---------------------------------------------------------------------------
// W GEMM:  W(2048 x 768) = X(2048 x 64) @ G(64 x 768)   (unchanged, proven)
// ---------------------------------------------------------------------------
__global__ void __launch_bounds__(256) wgemm_kernel(const float* __restrict__ xext,
                                                    int xsel, int fi) {
    const float* X = (xsel == 0) ? g_xa : (xsel == 1) ? g_xb : xext;
    const float* G = g_G[fi];

    __shared__ float xs[64][68];
    __shared__ float gs[64][128];

    int tid = threadIdx.x;
    int m0 = blockIdx.x * 64;
    int j0 = blockIdx.y * 128;

    for (int i = tid; i < 64 * 16; i += 256) {
        int row = i >> 4;
        int kq  = i & 15;
        float4 v = *(const float4*)&X[(size_t)(m0 + row) * D_N + kq * 4];
        xs[kq * 4 + 0][row] = v.x;
        xs[kq * 4 + 1][row] = v.y;
        xs[kq * 4 + 2][row] = v.z;
        xs[kq * 4 + 3][row] = v.w;
    }
    for (int i = tid; i < 64 * 32; i += 256) {
        int d  = i >> 5;
        int cq = i & 31;
        *(float4*)&gs[d][cq * 4] = *(const float4*)&G[(size_t)d * GN + j0 + cq * 4];
    }
    __syncthreads();

    int tx = tid & 31;
    int ty = tid >> 5;
    float acc[8][4];
#pragma unroll
    for (int im = 0; im < 8; ++im)
#pragma unroll
        for (int jn = 0; jn < 4; ++jn) acc[im][jn] = 0.f;

#pragma unroll 4
    for (int k = 0; k < 64; ++k) {
        float4 a0 = *(const float4*)&xs[k][ty * 8];
        float4 a1 = *(const float4*)&xs[k][ty * 8 + 4];
        float4 b  = *(const float4*)&gs[k][tx * 4];
        float av[8] = {a0.x, a0.y, a0.z, a0.w, a1.x, a1.y, a1.z, a1.w};
        float bv[4] = {b.x, b.y, b.z, b.w};
#pragma unroll
        for (int im = 0; im < 8; ++im)
#pragma unroll
            for (int jn = 0; jn < 4; ++jn) acc[im][jn] += av[im] * bv[jn];
    }

#pragma unroll
    for (int im = 0; im < 8; ++im) {
        size_t row = (size_t)(m0 + ty * 8 + im);
        *(float4*)&g_W[row * GN + j0 + tx * 4] =
            make_float4(acc[im][0], acc[im][1], acc[im][2], acc[im][3]);
    }
}

// ---------------------------------------------------------------------------
// Transpose+split W[k][o] fp32 -> Wt_hi/lo[o][k] bf16   (grid 384, 256 thr)
// ---------------------------------------------------------------------------
__global__ void __launch_bounds__(256) wtsplit_kernel() {
    __shared__ float ws[64][65];
    int kb = blockIdx.x * 64;
    int tid = threadIdx.x;
    for (int i = tid; i < 1024; i += 256) {
        int k = i >> 4, oq = i & 15;
        float4 v = *(const float4*)&g_W[(size_t)(kb + k) * D_N + oq * 4];
        ws[k][oq * 4 + 0] = v.x;
        ws[k][oq * 4 + 1] = v.y;
        ws[k][oq * 4 + 2] = v.z;
        ws[k][oq * 4 + 3] = v.w;
    }
    __syncthreads();
    for (int i = tid; i < 4096; i += 256) {
        int o = i >> 6, k = i & 63;
        __nv_bfloat16 h, l;
        split_bf16(ws[k][o], h, l);
        g_wth[(size_t)o * K_N + kb + k] = h;
        g_wtl[(size_t)o * K_N + kb + k] = l;
    }
}

// ---------------------------------------------------------------------------
// Tensor GEMM via warp-level mma.sync (split-bf16, 3 terms, split-K).
// A (conn) read as fp32, split to hi/lo bf16 on the fly in registers:
//   A: LDG (distance 2, regs) -> cvt+STS (distance 1), 2-stage ring
//   B: cp.async 3-stage ring; issueB(kt+2) targets stage (kt-1)%3 whose
//      reads completed before this iteration's __syncthreads() (no race).
// grid (16, 9), 256 threads = 8 warps (4 M x 2 N), warp tile 32x32, BK=32.
// ---------------------------------------------------------------------------
__global__ void __launch_bounds__(256, 1) mma_gemm_kernel(const float* __restrict__ conn) {
    extern __shared__ char smem[];
    unsigned sb = smem_u32(smem);
    int tid  = threadIdx.x;
    int lane = tid & 31;
    int wid  = tid >> 5;
    int wm   = wid & 3;          // warp M index (32 rows each)
    int wn   = wid >> 2;         // warp N index (32 cols each)
    int mbase = blockIdx.x * 128;
    int s     = blockIdx.y;
    int kt0   = s * KT_PER;
    int nkt   = (s < 8) ? KT_PER : (KT_TOTAL - 8 * KT_PER);

    // ldmatrix lane-address offsets (bytes, within a region)
    int a_row = lane & 15;
    int a_kad = (lane >> 4) * 8;
    unsigned aoff = (unsigned)((wm * 32 + a_row) * 80 + a_kad * 2);
    int bg  = lane >> 3;
    int b_n = (bg >> 1) * 8 + (lane & 7);
    int b_k = (bg & 1) * 8;
    unsigned boff = (unsigned)((wn * 32 + b_n) * 80 + b_k * 2);

    float c[2][4][4];
#pragma unroll
    for (int mf = 0; mf < 2; ++mf)
#pragma unroll
        for (int nf = 0; nf < 4; ++nf)
#pragma unroll
            for (int q = 0; q < 4; ++q) c[mf][nf][q] = 0.f;

    // A loader: thread covers row r = tid>>1, k-half h = tid&1 (16 fp32 each)
    const int ar = tid >> 1;
    const int ah = tid & 1;
    const float* pA = conn + (size_t)(mbase + ar) * K_N + (size_t)kt0 * 32 + ah * 16;

    float4 abuf[2][4];
    auto ldgA = [&](int t, int b) {
        const float* p = pA + (size_t)t * 32;
#pragma unroll
        for (int j = 0; j < 4; ++j) abuf[b][j] = *(const float4*)(p + j * 4);
    };
    auto stsA = [&](int b, int st) {
        unsigned hw[8], lw[8];
#pragma unroll
        for (int j = 0; j < 4; ++j) {
            float4 v = abuf[b][j];
            __nv_bfloat162 h0 = __floats2bfloat162_rn(v.x, v.y);
            __nv_bfloat162 h1 = __floats2bfloat162_rn(v.z, v.w);
            float2 h0f = __bfloat1622float2(h0);
            float2 h1f = __bfloat1622float2(h1);
            __nv_bfloat162 l0 = __floats2bfloat162_rn(v.x - h0f.x, v.y - h0f.y);
            __nv_bfloat162 l1 = __floats2bfloat162_rn(v.z - h1f.x, v.w - h1f.y);
            hw[2 * j + 0] = *(unsigned*)&h0;
            hw[2 * j + 1] = *(unsigned*)&h1;
            lw[2 * j + 0] = *(unsigned*)&l0;
            lw[2 * j + 1] = *(unsigned*)&l1;
        }
        char* stg = smem + st * A_ST_SZ;
        unsigned ro = (unsigned)(ar * 80 + ah * 32);
        *(uint4*)(stg + A_AH + ro)      = make_uint4(hw[0], hw[1], hw[2], hw[3]);
        *(uint4*)(stg + A_AH + ro + 16) = make_uint4(hw[4], hw[5], hw[6], hw[7]);
        *(uint4*)(stg + A_AL + ro)      = make_uint4(lw[0], lw[1], lw[2], lw[3]);
        *(uint4*)(stg + A_AL + ro + 16) = make_uint4(lw[4], lw[5], lw[6], lw[7]);
    };
    auto issueB = [&](int t) {
        unsigned stg = sb + B_BASE + (unsigned)(t % 3) * B_ST_SZ;
        size_t kk = (size_t)(kt0 + t) * 32;
#pragma unroll
        for (int j = 0; j < 2; ++j) {
            int i  = j * 256 + tid;
            int hb = i >> 8;
            int rr = (i >> 2) & 63;
            int cc = i & 3;
            const __nv_bfloat16* src =
                (hb ? g_wtl : g_wth) + (size_t)rr * K_N + kk + cc * 8;
            cpasync16(stg + (hb ? B_BL : B_BH) + (unsigned)(rr * 80 + cc * 16), src);
        }
    };

    // prologue (nkt >= 80)
    ldgA(0, 0);
    ldgA(1, 1);
    issueB(0); cp_commit();
    issueB(1); cp_commit();
    stsA(0, 0);

    for (int kt = 0; kt < nkt; ++kt) {
        cp_wait<1>();          // B(kt) complete (<=1 newer group pending)
        __syncthreads();       // A(kt) STS visible; all reads of reused stages done

        if (kt + 1 < nkt) stsA((kt + 1) & 1, (kt + 1) & 1);
        if (kt + 2 < nkt) {
            ldgA(kt + 2, kt & 1);
            issueB(kt + 2);    // B stage (kt+2)%3 == (kt-1)%3: reads sealed above
        }
        cp_commit();           // exactly one group per iteration

        unsigned astg = sb + (unsigned)(kt & 1) * A_ST_SZ;
        unsigned bstg = sb + B_BASE + (unsigned)(kt % 3) * B_ST_SZ;
#pragma unroll
        for (int ks = 0; ks < 2; ++ks) {
            unsigned kof = (unsigned)(ks * 32);   // 16 elems * 2B
            unsigned ahr[2][4], alr[2][4], bH[2][4], bL[2][4];
#pragma unroll
            for (int mf = 0; mf < 2; ++mf)
                ldmx4(ahr[mf], astg + A_AH + aoff + mf * 1280 + kof);
#pragma unroll
            for (int mf = 0; mf < 2; ++mf)
                ldmx4(alr[mf], astg + A_AL + aoff + mf * 1280 + kof);
#pragma unroll
            for (int nf2 = 0; nf2 < 2; ++nf2)
                ldmx4(bH[nf2], bstg + B_BH + boff + nf2 * 1280 + kof);
#pragma unroll
            for (int nf2 = 0; nf2 < 2; ++nf2)
                ldmx4(bL[nf2], bstg + B_BL + boff + nf2 * 1280 + kof);
#pragma unroll
            for (int mf = 0; mf < 2; ++mf)
#pragma unroll
                for (int nf = 0; nf < 4; ++nf) {
                    unsigned b0h = bH[nf >> 1][(nf & 1) * 2 + 0];
                    unsigned b1h = bH[nf >> 1][(nf & 1) * 2 + 1];
                    unsigned b0l = bL[nf >> 1][(nf & 1) * 2 + 0];
                    unsigned b1l = bL[nf >> 1][(nf & 1) * 2 + 1];
                    hmma(c[mf][nf], ahr[mf], b0h, b1h);   // hi*hi
                    hmma(c[mf][nf], alr[mf], b0h, b1h);   // lo*hi
                    hmma(c[mf][nf], ahr[mf], b0l, b1l);   // hi*lo
                }
        }
    }

    // epilogue: write split-K partials (deterministic buffers)
    float* op = &g_part[s][0];
#pragma unroll
    for (int mf = 0; mf < 2; ++mf)
#pragma unroll
        for (int nf = 0; nf < 4; ++nf) {
            int r0  = mbase + wm * 32 + mf * 16 + (lane >> 2);
            int col = wn * 32 + nf * 8 + (lane & 3) * 2;
            *(float2*)&op[(size_t)r0 * D_N + col] =
                make_float2(c[mf][nf][0], c[mf][nf][1]);
            *(float2*)&op[(size_t)(r0 + 8) * D_N + col] =
                make_float2(c[mf][nf][2], c[mf][nf][3]);
        }
}

// ---------------------------------------------------------------------------
// Reduce split-K partials + epilogue (bond term [+ residual] + ReLU)
// ---------------------------------------------------------------------------
__global__ void reduce_kernel(const float* __restrict__ xres, int fi,
                              float* __restrict__ oext, int osel) {
    int i = blockIdx.x * blockDim.x + threadIdx.x;
    if (i >= A_N * D_N) return;
    float acc = g_bt[fi][i];
#pragma unroll
    for (int p = 0; p < NSPLIT; ++p) acc += g_part[p][i];
    if (xres) acc += xres[i];
    acc = fmaxf(acc, 0.f);
    float* out = (osel == 0) ? g_xa : (osel == 1) ? g_xb : oext;
    out[i] = acc;
}

// ---------------------------------------------------------------------------
// Launch: 4 conv stages (relu; +x relu) x 2 filters, each filter used twice
// ---------------------------------------------------------------------------
extern "C" void kernel_launch(void* const* d_in, const int* in_sizes, int n_in,
                              void* d_out, int out_size) {
    const float* x    = (const float*)d_in[0];   // (2048, 64)
    const float* conn = (const float*)d_in[1];   // (2048, 2048, 12)
    const float* bond = (const float*)d_in[2];   // (2048, 12, 2)
    const float* f0   = (const float*)d_in[3];   // (64, 12, 66)
    const float* f1   = (const float*)d_in[4];   // (64, 12, 66)
    float* out = (float*)d_out;

    cudaFuncSetAttribute(mma_gemm_kernel,
                         cudaFuncAttributeMaxDynamicSharedMemorySize, TC_SMEM);

    prep_g_kernel<<<(2 * D_N * GN + 255) / 256, 256>>>(f0, f1);
    prep_bt_kernel<<<(2 * A_N * D_N + 255) / 256, 256>>>(bond, f0, f1);

    dim3 wgrid(32, 6);
    dim3 tgrid(16, NSPLIT);
    int rblocks = (A_N * D_N + 255) / 256;

    // stage 0: y = relu(conv(x, f0))                -> g_xa
    wgemm_kernel<<<wgrid, 256>>>(x, 2, 0);
    wtsplit_kernel<<<KT_TOTAL / 2, 256>>>();
    mma_gemm_kernel<<<tgrid, 256, TC_SMEM>>>(conn);
    reduce_kernel<<<rblocks, 256>>>(nullptr, 0, nullptr, 0);

    // stage 1: y = relu(conv(y, f0) + x)            -> g_xb
    wgemm_kernel<<<wgrid, 256>>>(nullptr, 0, 0);
    wtsplit_kernel<<<KT_TOTAL / 2, 256>>>();
    mma_gemm_kernel<<<tgrid, 256, TC_SMEM>>>(conn);
    reduce_kernel<<<rblocks, 256>>>(x, 0, nullptr, 1);

    // stage 2: y = relu(conv(y, f1))                -> g_xa
    wgemm_kernel<<<wgrid, 256>>>(nullptr, 1, 1);
    wtsplit_kernel<<<KT_TOTAL / 2, 256>>>();
    mma_gemm_kernel<<<tgrid, 256, TC_SMEM>>>(conn);
    reduce_kernel<<<rblocks, 256>>>(nullptr, 1, nullptr, 0);

    // stage 3: y = relu(conv(y, f1) + x)            -> d_out
    wgemm_kernel<<<wgrid, 256>>>(nullptr, 0, 1);
    wtsplit_kernel<<<KT_TOTAL / 2, 256>>>();
    mma_gemm_kernel<<<tgrid, 256, TC_SMEM>>>(conn);
    reduce_kernel<<<rblocks, 256>>>(x, 1, out, 2);
}

// round 13
// speedup vs baseline: 1.1834x; 1.1834x over previous
#include <cuda_runtime.h>
#include <cuda_bf16.h>

// Problem constants
#define A_N 2048
#define D_N 64
#define F_N 12
#define K_N (A_N * F_N)   // 24576
#define C_N 66            // D + 2
#define GN  (F_N * D_N)   // 768

// Split-K for the tensor GEMM: 16 M-tiles x 9 K-splits = 144 CTAs (one wave)
#define NSPLIT 9
#define KT_TOTAL 768          // 24576 / 32 K-tiles (BK=32)
#define KT_PER   86           // splits 0..7: 86 tiles, split 8: 80

// mma_gemm smem: A = 2 stages x 20480B, B = 3 stages x 10240B
// (rows padded to 80B for conflict-free ldmatrix)
#define A_ST_SZ 20480
#define A_AH    0
#define A_AL    10240
#define B_BASE  (2 * A_ST_SZ)        // 40960
#define B_ST_SZ 10240
#define B_BH    0
#define B_BL    5120
#define TC_SMEM (B_BASE + 3 * B_ST_SZ)   // 71680

// ---------------------------------------------------------------------------
// Scratch (device globals only — no allocation allowed)
// ---------------------------------------------------------------------------
__device__ __nv_bfloat16 g_wth[(size_t)D_N * K_N];  // Wt hi: [o][k] K-major
__device__ __nv_bfloat16 g_wtl[(size_t)D_N * K_N];  // Wt lo: [o][k]
__device__ float g_G[2][D_N * GN];
__device__ float g_bt[2][A_N * D_N];
__device__ float g_W[K_N * D_N];                    // W[k][o] fp32 (wgemm out)
__device__ float g_xa[A_N * D_N];
__device__ float g_xb[A_N * D_N];
__device__ float g_part[NSPLIT][A_N * D_N];

// ---------------------------------------------------------------------------
// PTX helpers (all baseline sm_80-era: no arch-suffix-gated features)
// ---------------------------------------------------------------------------
__device__ __forceinline__ unsigned smem_u32(const void* p) {
    unsigned a;
    asm("{ .reg .u64 t; cvta.to.shared.u64 t, %1; cvt.u32.u64 %0, t; }"
        : "=r"(a) : "l"(p));
    return a;
}
__device__ __forceinline__ void cpasync16(unsigned dst, const void* src) {
    asm volatile("cp.async.cg.shared.global [%0], [%1], 16;"
                 :: "r"(dst), "l"(src) : "memory");
}
__device__ __forceinline__ void cp_commit() {
    asm volatile("cp.async.commit_group;" ::: "memory");
}
template <int N>
__device__ __forceinline__ void cp_wait() {
    asm volatile("cp.async.wait_group %0;" :: "n"(N) : "memory");
}
__device__ __forceinline__ void ldmx4(unsigned r[4], unsigned addr) {
    asm volatile("ldmatrix.sync.aligned.m8n8.x4.shared.b16 {%0,%1,%2,%3}, [%4];"
                 : "=r"(r[0]), "=r"(r[1]), "=r"(r[2]), "=r"(r[3]) : "r"(addr));
}
__device__ __forceinline__ void hmma(float c[4], const unsigned a[4],
                                     unsigned b0, unsigned b1) {
    asm volatile(
        "mma.sync.aligned.m16n8k16.row.col.f32.bf16.bf16.f32 "
        "{%0,%1,%2,%3}, {%4,%5,%6,%7}, {%8,%9}, {%0,%1,%2,%3};"
        : "+f"(c[0]), "+f"(c[1]), "+f"(c[2]), "+f"(c[3])
        : "r"(a[0]), "r"(a[1]), "r"(a[2]), "r"(a[3]), "r"(b0), "r"(b1));
}
__device__ __forceinline__ void split_bf16(float x, __nv_bfloat16& h, __nv_bfloat16& l) {
    h = __float2bfloat16_rn(x);
    l = __float2bfloat16_rn(x - __bfloat162float(h));
}

// ---------------------------------------------------------------------------
// Prep: transpose filters into G
// ---------------------------------------------------------------------------
__global__ void prep_g_kernel(const float* __restrict__ f0, const float* __restrict__ f1) {
    int i = blockIdx.x * blockDim.x + threadIdx.x;
    if (i >= 2 * D_N * GN) return;
    int fi = i / (D_N * GN);
    int r  = i % (D_N * GN);
    int d  = r / GN;
    int j  = r % GN;
    int f  = j >> 6;
    int o  = j & 63;
    const float* filt = fi ? f1 : f0;
    g_G[fi][r] = filt[(o * F_N + f) * C_N + d];
}

// Prep: bond term (x-independent)
__global__ void prep_bt_kernel(const float* __restrict__ bond,
                               const float* __restrict__ f0,
                               const float* __restrict__ f1) {
    int i = blockIdx.x * blockDim.x + threadIdx.x;
    if (i >= 2 * A_N * D_N) return;
    int fi = i / (A_N * D_N);
    int r  = i % (A_N * D_N);
    int a  = r / D_N;
    int o  = r % D_N;
    const float* filt = fi ? f1 : f0;
    float s = 0.f;
#pragma unroll
    for (int f = 0; f < F_N; ++f) {
        s += bond[(a * F_N + f) * 2 + 0] * filt[(o * F_N + f) * C_N + 64];
        s += bond[(a * F_N + f) * 2 + 1] * filt[(o * F_N + f) * C_N + 65];
    }
    g_bt[fi][r] = s;
}

// ---------------------------------------------------------------------------
// W GEMM:  W(2048 x 768) = X(2048 x 64) @ G(64 x 768)   (unchanged, proven)
// ---------------------------------------------------------------------------
__global__ void __launch_bounds__(256) wgemm_kernel(const float* __restrict__ xext,
                                                    int xsel, int fi) {
    const float* X = (xsel == 0) ? g_xa : (xsel == 1) ? g_xb : xext;
    const float* G = g_G[fi];

    __shared__ float xs[64][68];
    __shared__ float gs[64][128];

    int tid = threadIdx.x;
    int m0 = blockIdx.x * 64;
    int j0 = blockIdx.y * 128;

    for (int i = tid; i < 64 * 16; i += 256) {
        int row = i >> 4;
        int kq  = i & 15;
        float4 v = *(const float4*)&X[(size_t)(m0 + row) * D_N + kq * 4];
        xs[kq * 4 + 0][row] = v.x;
        xs[kq * 4 + 1][row] = v.y;
        xs[kq * 4 + 2][row] = v.z;
        xs[kq * 4 + 3][row] = v.w;
    }
    for (int i = tid; i < 64 * 32; i += 256) {
        int d  = i >> 5;
        int cq = i & 31;
        *(float4*)&gs[d][cq * 4] = *(const float4*)&G[(size_t)d * GN + j0 + cq * 4];
    }
    __syncthreads();

    int tx = tid & 31;
    int ty = tid >> 5;
    float acc[8][4];
#pragma unroll
    for (int im = 0; im < 8; ++im)
#pragma unroll
        for (int jn = 0; jn < 4; ++jn) acc[im][jn] = 0.f;

#pragma unroll 4
    for (int k = 0; k < 64; ++k) {
        float4 a0 = *(const float4*)&xs[k][ty * 8];
        float4 a1 = *(const float4*)&xs[k][ty * 8 + 4];
        float4 b  = *(const float4*)&gs[k][tx * 4];
        float av[8] = {a0.x, a0.y, a0.z, a0.w, a1.x, a1.y, a1.z, a1.w};
        float bv[4] = {b.x, b.y, b.z, b.w};
#pragma unroll
        for (int im = 0; im < 8; ++im)
#pragma unroll
            for (int jn = 0; jn < 4; ++jn) acc[im][jn] += av[im] * bv[jn];
    }

#pragma unroll
    for (int im = 0; im < 8; ++im) {
        size_t row = (size_t)(m0 + ty * 8 + im);
        *(float4*)&g_W[row * GN + j0 + tx * 4] =
            make_float4(acc[im][0], acc[im][1], acc[im][2], acc[im][3]);
    }
}

// ---------------------------------------------------------------------------
// Transpose+split W[k][o] fp32 -> Wt_hi/lo[o][k] bf16   (grid 384, 256 thr)
// ---------------------------------------------------------------------------
__global__ void __launch_bounds__(256) wtsplit_kernel() {
    __shared__ float ws[64][65];
    int kb = blockIdx.x * 64;
    int tid = threadIdx.x;
    for (int i = tid; i < 1024; i += 256) {
        int k = i >> 4, oq = i & 15;
        float4 v = *(const float4*)&g_W[(size_t)(kb + k) * D_N + oq * 4];
        ws[k][oq * 4 + 0] = v.x;
        ws[k][oq * 4 + 1] = v.y;
        ws[k][oq * 4 + 2] = v.z;
        ws[k][oq * 4 + 3] = v.w;
    }
    __syncthreads();
    for (int i = tid; i < 4096; i += 256) {
        int o = i >> 6, k = i & 63;
        __nv_bfloat16 h, l;
        split_bf16(ws[k][o], h, l);
        g_wth[(size_t)o * K_N + kb + k] = h;
        g_wtl[(size_t)o * K_N + kb + k] = l;
    }
}

// ---------------------------------------------------------------------------
// Tensor GEMM via warp-level mma.sync (split-bf16, 3 terms, split-K).
// A (conn) read as fp32, split to hi/lo bf16 on the fly in registers.
// Loop order per iteration (latency-hiding critical):
//   wait/sync -> ldgA(kt+2) -> COMPUTE(kt) -> stsA(kt+1) -> issueB(kt+2)
// so the LDG->STS distance is ~2 full compute bodies (no exposed DRAM stall).
// A: 2-stage smem ring; B: cp.async 3-stage ring (issueB(kt+2) targets stage
// (kt-1)%3 whose reads were sealed by this iteration's barrier).
// grid (16, 9), 256 threads = 8 warps (4 M x 2 N), warp tile 32x32, BK=32.
// ---------------------------------------------------------------------------
__global__ void __launch_bounds__(256, 1) mma_gemm_kernel(const float* __restrict__ conn) {
    extern __shared__ char smem[];
    unsigned sb = smem_u32(smem);
    int tid  = threadIdx.x;
    int lane = tid & 31;
    int wid  = tid >> 5;
    int wm   = wid & 3;          // warp M index (32 rows each)
    int wn   = wid >> 2;         // warp N index (32 cols each)
    int mbase = blockIdx.x * 128;
    int s     = blockIdx.y;
    int kt0   = s * KT_PER;
    int nkt   = (s < 8) ? KT_PER : (KT_TOTAL - 8 * KT_PER);

    // ldmatrix lane-address offsets (bytes, within a region)
    int a_row = lane & 15;
    int a_kad = (lane >> 4) * 8;
    unsigned aoff = (unsigned)((wm * 32 + a_row) * 80 + a_kad * 2);
    int bg  = lane >> 3;
    int b_n = (bg >> 1) * 8 + (lane & 7);
    int b_k = (bg & 1) * 8;
    unsigned boff = (unsigned)((wn * 32 + b_n) * 80 + b_k * 2);

    float c[2][4][4];
#pragma unroll
    for (int mf = 0; mf < 2; ++mf)
#pragma unroll
        for (int nf = 0; nf < 4; ++nf)
#pragma unroll
            for (int q = 0; q < 4; ++q) c[mf][nf][q] = 0.f;

    // A loader: thread covers row r = tid>>1, k-half h = tid&1 (16 fp32 each)
    const int ar = tid >> 1;
    const int ah = tid & 1;
    const float* pA = conn + (size_t)(mbase + ar) * K_N + (size_t)kt0 * 32 + ah * 16;

    float4 abuf[2][4];
    auto ldgA = [&](int t, int b) {
        const float* p = pA + (size_t)t * 32;
#pragma unroll
        for (int j = 0; j < 4; ++j) abuf[b][j] = *(const float4*)(p + j * 4);
    };
    auto stsA = [&](int b, int st) {
        unsigned hw[8], lw[8];
#pragma unroll
        for (int j = 0; j < 4; ++j) {
            float4 v = abuf[b][j];
            __nv_bfloat162 h0 = __floats2bfloat162_rn(v.x, v.y);
            __nv_bfloat162 h1 = __floats2bfloat162_rn(v.z, v.w);
            float2 h0f = __bfloat1622float2(h0);
            float2 h1f = __bfloat1622float2(h1);
            __nv_bfloat162 l0 = __floats2bfloat162_rn(v.x - h0f.x, v.y - h0f.y);
            __nv_bfloat162 l1 = __floats2bfloat162_rn(v.z - h1f.x, v.w - h1f.y);
            hw[2 * j + 0] = *(unsigned*)&h0;
            hw[2 * j + 1] = *(unsigned*)&h1;
            lw[2 * j + 0] = *(unsigned*)&l0;
            lw[2 * j + 1] = *(unsigned*)&l1;
        }
        char* stg = smem + st * A_ST_SZ;
        unsigned ro = (unsigned)(ar * 80 + ah * 32);
        *(uint4*)(stg + A_AH + ro)      = make_uint4(hw[0], hw[1], hw[2], hw[3]);
        *(uint4*)(stg + A_AH + ro + 16) = make_uint4(hw[4], hw[5], hw[6], hw[7]);
        *(uint4*)(stg + A_AL + ro)      = make_uint4(lw[0], lw[1], lw[2], lw[3]);
        *(uint4*)(stg + A_AL + ro + 16) = make_uint4(lw[4], lw[5], lw[6], lw[7]);
    };
    auto issueB = [&](int t) {
        unsigned stg = sb + B_BASE + (unsigned)(t % 3) * B_ST_SZ;
        size_t kk = (size_t)(kt0 + t) * 32;
#pragma unroll
        for (int j = 0; j < 2; ++j) {
            int i  = j * 256 + tid;
            int hb = i >> 8;
            int rr = (i >> 2) & 63;
            int cc = i & 3;
            const __nv_bfloat16* src =
                (hb ? g_wtl : g_wth) + (size_t)rr * K_N + kk + cc * 8;
            cpasync16(stg + (hb ? B_BL : B_BH) + (unsigned)(rr * 80 + cc * 16), src);
        }
    };

    // prologue (nkt >= 80)
    ldgA(0, 0);
    ldgA(1, 1);
    issueB(0); cp_commit();
    issueB(1); cp_commit();
    stsA(0, 0);

    for (int kt = 0; kt < nkt; ++kt) {
        cp_wait<1>();          // B(kt) complete (<=1 newer group pending)
        __syncthreads();       // A(kt) STS visible; reads of reused stages sealed

        // LDG early: consumed by stsA at the END of the NEXT iteration
        // (~2 compute bodies of slack; buf kt&1 was drained by stsA(kt)).
        if (kt + 2 < nkt) ldgA(kt + 2, kt & 1);

        unsigned astg = sb + (unsigned)(kt & 1) * A_ST_SZ;
        unsigned bstg = sb + B_BASE + (unsigned)(kt % 3) * B_ST_SZ;
#pragma unroll
        for (int ks = 0; ks < 2; ++ks) {
            unsigned kof = (unsigned)(ks * 32);   // 16 elems * 2B
            unsigned ahr[2][4], alr[2][4], bH[2][4], bL[2][4];
#pragma unroll
            for (int mf = 0; mf < 2; ++mf)
                ldmx4(ahr[mf], astg + A_AH + aoff + mf * 1280 + kof);
#pragma unroll
            for (int mf = 0; mf < 2; ++mf)
                ldmx4(alr[mf], astg + A_AL + aoff + mf * 1280 + kof);
#pragma unroll
            for (int nf2 = 0; nf2 < 2; ++nf2)
                ldmx4(bH[nf2], bstg + B_BH + boff + nf2 * 1280 + kof);
#pragma unroll
            for (int nf2 = 0; nf2 < 2; ++nf2)
                ldmx4(bL[nf2], bstg + B_BL + boff + nf2 * 1280 + kof);
#pragma unroll
            for (int mf = 0; mf < 2; ++mf)
#pragma unroll
                for (int nf = 0; nf < 4; ++nf) {
                    unsigned b0h = bH[nf >> 1][(nf & 1) * 2 + 0];
                    unsigned b1h = bH[nf >> 1][(nf & 1) * 2 + 1];
                    unsigned b0l = bL[nf >> 1][(nf & 1) * 2 + 0];
                    unsigned b1l = bL[nf >> 1][(nf & 1) * 2 + 1];
                    hmma(c[mf][nf], ahr[mf], b0h, b1h);   // hi*hi
                    hmma(c[mf][nf], alr[mf], b0h, b1h);   // lo*hi
                    hmma(c[mf][nf], ahr[mf], b0l, b1l);   // hi*lo
                }
        }

        // post-compute: stage A(kt+1) (region last read in iter kt-1, sealed),
        // then B(kt+2) into stage (kt-1)%3 (same proven invariant).
        if (kt + 1 < nkt) stsA((kt + 1) & 1, (kt + 1) & 1);
        if (kt + 2 < nkt) issueB(kt + 2);
        cp_commit();           // exactly one group per iteration
    }

    // epilogue: write split-K partials (deterministic buffers)
    float* op = &g_part[s][0];
#pragma unroll
    for (int mf = 0; mf < 2; ++mf)
#pragma unroll
        for (int nf = 0; nf < 4; ++nf) {
            int r0  = mbase + wm * 32 + mf * 16 + (lane >> 2);
            int col = wn * 32 + nf * 8 + (lane & 3) * 2;
            *(float2*)&op[(size_t)r0 * D_N + col] =
                make_float2(c[mf][nf][0], c[mf][nf][1]);
            *(float2*)&op[(size_t)(r0 + 8) * D_N + col] =
                make_float2(c[mf][nf][2], c[mf][nf][3]);
        }
}

// ---------------------------------------------------------------------------
// Reduce split-K partials + epilogue (bond term [+ residual] + ReLU)
// ---------------------------------------------------------------------------
__global__ void reduce_kernel(const float* __restrict__ xres, int fi,
                              float* __restrict__ oext, int osel) {
    int i = blockIdx.x * blockDim.x + threadIdx.x;
    if (i >= A_N * D_N) return;
    float acc = g_bt[fi][i];
#pragma unroll
    for (int p = 0; p < NSPLIT; ++p) acc += g_part[p][i];
    if (xres) acc += xres[i];
    acc = fmaxf(acc, 0.f);
    float* out = (osel == 0) ? g_xa : (osel == 1) ? g_xb : oext;
    out[i] = acc;
}

// ---------------------------------------------------------------------------
// Launch: 4 conv stages (relu; +x relu) x 2 filters, each filter used twice
// ---------------------------------------------------------------------------
extern "C" void kernel_launch(void* const* d_in, const int* in_sizes, int n_in,
                              void* d_out, int out_size) {
    const float* x    = (const float*)d_in[0];   // (2048, 64)
    const float* conn = (const float*)d_in[1];   // (2048, 2048, 12)
    const float* bond = (const float*)d_in[2];   // (2048, 12, 2)
    const float* f0   = (const float*)d_in[3];   // (64, 12, 66)
    const float* f1   = (const float*)d_in[4];   // (64, 12, 66)
    float* out = (float*)d_out;

    cudaFuncSetAttribute(mma_gemm_kernel,
                         cudaFuncAttributeMaxDynamicSharedMemorySize, TC_SMEM);

    prep_g_kernel<<<(2 * D_N * GN + 255) / 256, 256>>>(f0, f1);
    prep_bt_kernel<<<(2 * A_N * D_N + 255) / 256, 256>>>(bond, f0, f1);

    dim3 wgrid(32, 6);
    dim3 tgrid(16, NSPLIT);
    int rblocks = (A_N * D_N + 255) / 256;

    // stage 0: y = relu(conv(x, f0))                -> g_xa
    wgemm_kernel<<<wgrid, 256>>>(x, 2, 0);
    wtsplit_kernel<<<KT_TOTAL / 2, 256>>>();
    mma_gemm_kernel<<<tgrid, 256, TC_SMEM>>>(conn);
    reduce_kernel<<<rblocks, 256>>>(nullptr, 0, nullptr, 0);

    // stage 1: y = relu(conv(y, f0) + x)            -> g_xb
    wgemm_kernel<<<wgrid, 256>>>(nullptr, 0, 0);
    wtsplit_kernel<<<KT_TOTAL / 2, 256>>>();
    mma_gemm_kernel<<<tgrid, 256, TC_SMEM>>>(conn);
    reduce_kernel<<<rblocks, 256>>>(x, 0, nullptr, 1);

    // stage 2: y = relu(conv(y, f1))                -> g_xa
    wgemm_kernel<<<wgrid, 256>>>(nullptr, 1, 1);
    wtsplit_kernel<<<KT_TOTAL / 2, 256>>>();
    mma_gemm_kernel<<<tgrid, 256, TC_SMEM>>>(conn);
    reduce_kernel<<<rblocks, 256>>>(nullptr, 1, nullptr, 0);

    // stage 3: y = relu(conv(y, f1) + x)            -> d_out
    wgemm_kernel<<<wgrid, 256>>>(nullptr, 0, 1);
    wtsplit_kernel<<<KT_TOTAL / 2, 256>>>();
    mma_gemm_kernel<<<tgrid, 256, TC_SMEM>>>(conn);
    reduce_kernel<<<rblocks, 256>>>(x, 1, out, 2);
}

// round 15
// speedup vs baseline: 1.6829x; 1.4220x over previous
#include <cuda_runtime.h>
#include <cuda_bf16.h>

// Problem constants
#define A_N 2048
#define D_N 64
#define F_N 12
#define K_N (A_N * F_N)   // 24576
#define C_N 66            // D + 2
#define GN  (F_N * D_N)   // 768

// Split-K for the tensor GEMM: 16 M-tiles x 18 K-splits = 288 CTAs
// (2 CTAs/SM at occupancy 2 -> one wave on 148 SMs)
#define NSPLIT 18
#define KT_TOTAL 768          // 24576 / 32 K-tiles (BK=32)
#define KT_PER   43           // splits 0..16: 43 tiles, split 17: 37

// mma_gemm smem: 3 stages x 30720B (rows padded to 80B, conflict-free ldmatrix)
#define ST_AH 0
#define ST_AL 10240
#define ST_BH 20480
#define ST_BL 25600
#define ST_SZ 30720
#define TC_SMEM (3 * ST_SZ)   // 92160 -> 2 CTAs/SM (184320 <= 228KB)

// ---------------------------------------------------------------------------
// Scratch (device globals only — no allocation allowed)
// ---------------------------------------------------------------------------
__device__ __nv_bfloat16 g_ch[(size_t)A_N * K_N];   // conn hi (bf16)
__device__ __nv_bfloat16 g_cl[(size_t)A_N * K_N];   // conn lo (bf16 residual)
__device__ __nv_bfloat16 g_wth[(size_t)D_N * K_N];  // Wt hi: [o][k] K-major
__device__ __nv_bfloat16 g_wtl[(size_t)D_N * K_N];  // Wt lo: [o][k]
__device__ float g_G[2][D_N * GN];
__device__ float g_bt[2][A_N * D_N];
__device__ float g_W[K_N * D_N];                    // W[k][o] fp32 (wgemm out)
__device__ float g_xa[A_N * D_N];
__device__ float g_xb[A_N * D_N];
__device__ float g_part[NSPLIT][A_N * D_N];

// ---------------------------------------------------------------------------
// PTX helpers (all baseline sm_80-era: no arch-suffix-gated features)
// ---------------------------------------------------------------------------
__device__ __forceinline__ unsigned smem_u32(const void* p) {
    unsigned a;
    asm("{ .reg .u64 t; cvta.to.shared.u64 t, %1; cvt.u32.u64 %0, t; }"
        : "=r"(a) : "l"(p));
    return a;
}
__device__ __forceinline__ void cpasync16(unsigned dst, const void* src) {
    asm volatile("cp.async.cg.shared.global [%0], [%1], 16;"
                 :: "r"(dst), "l"(src) : "memory");
}
__device__ __forceinline__ void cp_commit() {
    asm volatile("cp.async.commit_group;" ::: "memory");
}
template <int N>
__device__ __forceinline__ void cp_wait() {
    asm volatile("cp.async.wait_group %0;" :: "n"(N) : "memory");
}
__device__ __forceinline__ void ldmx4(unsigned r[4], unsigned addr) {
    asm volatile("ldmatrix.sync.aligned.m8n8.x4.shared.b16 {%0,%1,%2,%3}, [%4];"
                 : "=r"(r[0]), "=r"(r[1]), "=r"(r[2]), "=r"(r[3]) : "r"(addr));
}
__device__ __forceinline__ void hmma(float c[4], const unsigned a[4],
                                     unsigned b0, unsigned b1) {
    asm volatile(
        "mma.sync.aligned.m16n8k16.row.col.f32.bf16.bf16.f32 "
        "{%0,%1,%2,%3}, {%4,%5,%6,%7}, {%8,%9}, {%0,%1,%2,%3};"
        : "+f"(c[0]), "+f"(c[1]), "+f"(c[2]), "+f"(c[3])
        : "r"(a[0]), "r"(a[1]), "r"(a[2]), "r"(a[3]), "r"(b0), "r"(b1));
}
__device__ __forceinline__ void split_bf16(float x, __nv_bfloat16& h, __nv_bfloat16& l) {
    h = __float2bfloat16_rn(x);
    l = __float2bfloat16_rn(x - __bfloat162float(h));
}

// ---------------------------------------------------------------------------
// One-time: conn fp32 -> (hi, lo) bf16 split
// ---------------------------------------------------------------------------
__global__ void __launch_bounds__(256) conv_split_kernel(const float* __restrict__ conn) {
    size_t i = (size_t)blockIdx.x * 256 + threadIdx.x;   // float4 index
    if (i >= (size_t)A_N * K_N / 4) return;
    float4 v = ((const float4*)conn)[i];
    __nv_bfloat16 h0, l0, h1, l1, h2, l2, h3, l3;
    split_bf16(v.x, h0, l0);
    split_bf16(v.y, h1, l1);
    split_bf16(v.z, h2, l2);
    split_bf16(v.w, h3, l3);
    union { __nv_bfloat16 b[4]; uint2 u; } ph, pl;
    ph.b[0] = h0; ph.b[1] = h1; ph.b[2] = h2; ph.b[3] = h3;
    pl.b[0] = l0; pl.b[1] = l1; pl.b[2] = l2; pl.b[3] = l3;
    ((uint2*)g_ch)[i] = ph.u;
    ((uint2*)g_cl)[i] = pl.u;
}

// ---------------------------------------------------------------------------
// Prep: transpose filters into G
// ---------------------------------------------------------------------------
__global__ void prep_g_kernel(const float* __restrict__ f0, const float* __restrict__ f1) {
    int i = blockIdx.x * blockDim.x + threadIdx.x;
    if (i >= 2 * D_N * GN) return;
    int fi = i / (D_N * GN);
    int r  = i % (D_N * GN);
    int d  = r / GN;
    int j  = r % GN;
    int f  = j >> 6;
    int o  = j & 63;
    const float* filt = fi ? f1 : f0;
    g_G[fi][r] = filt[(o * F_N + f) * C_N + d];
}

// Prep: bond term (x-independent)
__global__ void prep_bt_kernel(const float* __restrict__ bond,
                               const float* __restrict__ f0,
                               const float* __restrict__ f1) {
    int i = blockIdx.x * blockDim.x + threadIdx.x;
    if (i >= 2 * A_N * D_N) return;
    int fi = i / (A_N * D_N);
    int r  = i % (A_N * D_N);
    int a  = r / D_N;
    int o  = r % D_N;
    const float* filt = fi ? f1 : f0;
    float s = 0.f;
#pragma unroll
    for (int f = 0; f < F_N; ++f) {
        s += bond[(a * F_N + f) * 2 + 0] * filt[(o * F_N + f) * C_N + 64];
        s += bond[(a * F_N + f) * 2 + 1] * filt[(o * F_N + f) * C_N + 65];
    }
    g_bt[fi][r] = s;
}

// ---------------------------------------------------------------------------
// W GEMM:  W(2048 x 768) = X(2048 x 64) @ G(64 x 768)   (unchanged, proven)
// ---------------------------------------------------------------------------
__global__ void __launch_bounds__(256) wgemm_kernel(const float* __restrict__ xext,
                                                    int xsel, int fi) {
    const float* X = (xsel == 0) ? g_xa : (xsel == 1) ? g_xb : xext;
    const float* G = g_G[fi];

    __shared__ float xs[64][68];
    __shared__ float gs[64][128];

    int tid = threadIdx.x;
    int m0 = blockIdx.x * 64;
    int j0 = blockIdx.y * 128;

    for (int i = tid; i < 64 * 16; i += 256) {
        int row = i >> 4;
        int kq  = i & 15;
        float4 v = *(const float4*)&X[(size_t)(m0 + row) * D_N + kq * 4];
        xs[kq * 4 + 0][row] = v.x;
        xs[kq * 4 + 1][row] = v.y;
        xs[kq * 4 + 2][row] = v.z;
        xs[kq * 4 + 3][row] = v.w;
    }
    for (int i = tid; i < 64 * 32; i += 256) {
        int d  = i >> 5;
        int cq = i & 31;
        *(float4*)&gs[d][cq * 4] = *(const float4*)&G[(size_t)d * GN + j0 + cq * 4];
    }
    __syncthreads();

    int tx = tid & 31;
    int ty = tid >> 5;
    float acc[8][4];
#pragma unroll
    for (int im = 0; im < 8; ++im)
#pragma unroll
        for (int jn = 0; jn < 4; ++jn) acc[im][jn] = 0.f;

#pragma unroll 4
    for (int k = 0; k < 64; ++k) {
        float4 a0 = *(const float4*)&xs[k][ty * 8];
        float4 a1 = *(const float4*)&xs[k][ty * 8 + 4];
        float4 b  = *(const float4*)&gs[k][tx * 4];
        float av[8] = {a0.x, a0.y, a0.z, a0.w, a1.x, a1.y, a1.z, a1.w};
        float bv[4] = {b.x, b.y, b.z, b.w};
#pragma unroll
        for (int im = 0; im < 8; ++im)
#pragma unroll
            for (int jn = 0; jn < 4; ++jn) acc[im][jn] += av[im] * bv[jn];
    }

#pragma unroll
    for (int im = 0; im < 8; ++im) {
        size_t row = (size_t)(m0 + ty * 8 + im);
        *(float4*)&g_W[row * GN + j0 + tx * 4] =
            make_float4(acc[im][0], acc[im][1], acc[im][2], acc[im][3]);
    }
}

// ---------------------------------------------------------------------------
// Transpose+split W[k][o] fp32 -> Wt_hi/lo[o][k] bf16   (grid 384, 256 thr)
// ---------------------------------------------------------------------------
__global__ void __launch_bounds__(256) wtsplit_kernel() {
    __shared__ float ws[64][65];
    int kb = blockIdx.x * 64;
    int tid = threadIdx.x;
    for (int i = tid; i < 1024; i += 256) {
        int k = i >> 4, oq = i & 15;
        float4 v = *(const float4*)&g_W[(size_t)(kb + k) * D_N + oq * 4];
        ws[k][oq * 4 + 0] = v.x;
        ws[k][oq * 4 + 1] = v.y;
        ws[k][oq * 4 + 2] = v.z;
        ws[k][oq * 4 + 3] = v.w;
    }
    __syncthreads();
    for (int i = tid; i < 4096; i += 256) {
        int o = i >> 6, k = i & 63;
        __nv_bfloat16 h, l;
        split_bf16(ws[k][o], h, l);
        g_wth[(size_t)o * K_N + kb + k] = h;
        g_wtl[(size_t)o * K_N + kb + k] = l;
    }
}

// ---------------------------------------------------------------------------
// Tensor GEMM via warp-level mma.sync (split-bf16, 3 terms, split-K).
// R9-proven all-cp.async loader; 3-stage ring + occupancy 2 (2 CTAs/SM),
// grid (16, 18) = 288 CTAs = one wave at occ 2.
// load(kt+2) targets stage (kt+2)%3 == (kt-1)%3, sealed by this iteration's
// __syncthreads(). wait_group<1> keeps tile kt resident.
// 256 threads = 8 warps (4 M x 2 N), warp tile 32x32, BK=32.
// ---------------------------------------------------------------------------
__global__ void __launch_bounds__(256, 2) mma_gemm_kernel() {
    extern __shared__ char smem[];
    unsigned sb = smem_u32(smem);
    int tid  = threadIdx.x;
    int lane = tid & 31;
    int wid  = tid >> 5;
    int wm   = wid & 3;          // warp M index (32 rows each)
    int wn   = wid >> 2;         // warp N index (32 cols each)
    int mbase = blockIdx.x * 128;
    int s     = blockIdx.y;
    int kt0   = s * KT_PER;
    int nkt   = (s < NSPLIT - 1) ? KT_PER : (KT_TOTAL - (NSPLIT - 1) * KT_PER);

    // ldmatrix lane-address offsets (bytes, within a stage region)
    int a_row = lane & 15;
    int a_kad = (lane >> 4) * 8;
    unsigned aoff = (unsigned)((wm * 32 + a_row) * 80 + a_kad * 2);
    int bg  = lane >> 3;
    int b_n = (bg >> 1) * 8 + (lane & 7);
    int b_k = (bg & 1) * 8;
    unsigned boff = (unsigned)((wn * 32 + b_n) * 80 + b_k * 2);

    float c[2][4][4];
#pragma unroll
    for (int mf = 0; mf < 2; ++mf)
#pragma unroll
        for (int nf = 0; nf < 4; ++nf)
#pragma unroll
            for (int q = 0; q < 4; ++q) c[mf][nf][q] = 0.f;

    auto loadT = [&](int t) {
        unsigned stg = sb + (unsigned)(t % 3) * ST_SZ;
        size_t kk = (size_t)(kt0 + t) * 32;
        // A: 1024 x 16B chunks (hi 512 + lo 512), 4 per thread
#pragma unroll
        for (int j = 0; j < 4; ++j) {
            int i  = j * 256 + tid;
            int hi = i >> 9;
            int r  = (i >> 2) & 127;
            int cc = i & 3;
            const __nv_bfloat16* src =
                (hi ? g_cl : g_ch) + (size_t)(mbase + r) * K_N + kk + cc * 8;
            cpasync16(stg + (hi ? ST_AL : ST_AH) + (unsigned)(r * 80 + cc * 16), src);
        }
        // B: 512 chunks (hi 256 + lo 256), 2 per thread
#pragma unroll
        for (int j = 0; j < 2; ++j) {
            int i  = j * 256 + tid;
            int hb = i >> 8;
            int rr = (i >> 2) & 63;
            int cc = i & 3;
            const __nv_bfloat16* src =
                (hb ? g_wtl : g_wth) + (size_t)rr * K_N + kk + cc * 8;
            cpasync16(stg + (hb ? ST_BL : ST_BH) + (unsigned)(rr * 80 + cc * 16), src);
        }
    };

    // prologue: 2 tiles in flight (nkt >= 37)
    loadT(0); cp_commit();
    loadT(1); cp_commit();

    for (int kt = 0; kt < nkt; ++kt) {
        cp_wait<1>();          // tile kt complete (<=1 newer group pending)
        __syncthreads();       // reads of stage (kt-1)%3 sealed

        // fire next loads early (stage (kt+2)%3 == (kt-1)%3: sealed above)
        if (kt + 2 < nkt) loadT(kt + 2);
        cp_commit();           // exactly one group per iteration

        unsigned stg = sb + (unsigned)(kt % 3) * ST_SZ;
#pragma unroll
        for (int ks = 0; ks < 2; ++ks) {
            unsigned kof = (unsigned)(ks * 32);   // 16 elems * 2B
            unsigned ahr[2][4], alr[2][4], bH[2][4], bL[2][4];
#pragma unroll
            for (int mf = 0; mf < 2; ++mf)
                ldmx4(ahr[mf], stg + ST_AH + aoff + mf * 1280 + kof);
#pragma unroll
            for (int mf = 0; mf < 2; ++mf)
                ldmx4(alr[mf], stg + ST_AL + aoff + mf * 1280 + kof);
#pragma unroll
            for (int nf2 = 0; nf2 < 2; ++nf2)
                ldmx4(bH[nf2], stg + ST_BH + boff + nf2 * 1280 + kof);
#pragma unroll
            for (int nf2 = 0; nf2 < 2; ++nf2)
                ldmx4(bL[nf2], stg + ST_BL + boff + nf2 * 1280 + kof);
#pragma unroll
            for (int mf = 0; mf < 2; ++mf)
#pragma unroll
                for (int nf = 0; nf < 4; ++nf) {
                    unsigned b0h = bH[nf >> 1][(nf & 1) * 2 + 0];
                    unsigned b1h = bH[nf >> 1][(nf & 1) * 2 + 1];
                    unsigned b0l = bL[nf >> 1][(nf & 1) * 2 + 0];
                    unsigned b1l = bL[nf >> 1][(nf & 1) * 2 + 1];
                    hmma(c[mf][nf], ahr[mf], b0h, b1h);   // hi*hi
                    hmma(c[mf][nf], alr[mf], b0h, b1h);   // lo*hi
                    hmma(c[mf][nf], ahr[mf], b0l, b1l);   // hi*lo
                }
        }
    }

    // epilogue: write split-K partials (deterministic buffers)
    float* op = &g_part[s][0];
#pragma unroll
    for (int mf = 0; mf < 2; ++mf)
#pragma unroll
        for (int nf = 0; nf < 4; ++nf) {
            int r0  = mbase + wm * 32 + mf * 16 + (lane >> 2);
            int col = wn * 32 + nf * 8 + (lane & 3) * 2;
            *(float2*)&op[(size_t)r0 * D_N + col] =
                make_float2(c[mf][nf][0], c[mf][nf][1]);
            *(float2*)&op[(size_t)(r0 + 8) * D_N + col] =
                make_float2(c[mf][nf][2], c[mf][nf][3]);
        }
}

// ---------------------------------------------------------------------------
// Reduce split-K partials + epilogue (bond term [+ residual] + ReLU)
// ---------------------------------------------------------------------------
__global__ void reduce_kernel(const float* __restrict__ xres, int fi,
                              float* __restrict__ oext, int osel) {
    int i = blockIdx.x * blockDim.x + threadIdx.x;
    if (i >= A_N * D_N) return;
    float acc = g_bt[fi][i];
#pragma unroll
    for (int p = 0; p < NSPLIT; ++p) acc += g_part[p][i];
    if (xres) acc += xres[i];
    acc = fmaxf(acc, 0.f);
    float* out = (osel == 0) ? g_xa : (osel == 1) ? g_xb : oext;
    out[i] = acc;
}

// ---------------------------------------------------------------------------
// Launch: 4 conv stages (relu; +x relu) x 2 filters, each filter used twice
// ---------------------------------------------------------------------------
extern "C" void kernel_launch(void* const* d_in, const int* in_sizes, int n_in,
                              void* d_out, int out_size) {
    const float* x    = (const float*)d_in[0];   // (2048, 64)
    const float* conn = (const float*)d_in[1];   // (2048, 2048, 12)
    const float* bond = (const float*)d_in[2];   // (2048, 12, 2)
    const float* f0   = (const float*)d_in[3];   // (64, 12, 66)
    const float* f1   = (const float*)d_in[4];   // (64, 12, 66)
    float* out = (float*)d_out;

    cudaFuncSetAttribute(mma_gemm_kernel,
                         cudaFuncAttributeMaxDynamicSharedMemorySize, TC_SMEM);

    prep_g_kernel<<<(2 * D_N * GN + 255) / 256, 256>>>(f0, f1);
    prep_bt_kernel<<<(2 * A_N * D_N + 255) / 256, 256>>>(bond, f0, f1);

    // one-time split of conn into hi/lo bf16 (reused by all 4 stages)
    size_t nvec = (size_t)A_N * K_N / 4;
    conv_split_kernel<<<(unsigned)((nvec + 255) / 256), 256>>>(conn);

    dim3 wgrid(32, 6);
    dim3 tgrid(16, NSPLIT);
    int rblocks = (A_N * D_N + 255) / 256;

    // stage 0: y = relu(conv(x, f0))                -> g_xa
    wgemm_kernel<<<wgrid, 256>>>(x, 2, 0);
    wtsplit_kernel<<<KT_TOTAL / 2, 256>>>();
    mma_gemm_kernel<<<tgrid, 256, TC_SMEM>>>();
    reduce_kernel<<<rblocks, 256>>>(nullptr, 0, nullptr, 0);

    // stage 1: y = relu(conv(y, f0) + x)            -> g_xb
    wgemm_kernel<<<wgrid, 256>>>(nullptr, 0, 0);
    wtsplit_kernel<<<KT_TOTAL / 2, 256>>>();
    mma_gemm_kernel<<<tgrid, 256, TC_SMEM>>>();
    reduce_kernel<<<rblocks, 256>>>(x, 0, nullptr, 1);

    // stage 2: y = relu(conv(y, f1))                -> g_xa
    wgemm_kernel<<<wgrid, 256>>>(nullptr, 1, 1);
    wtsplit_kernel<<<KT_TOTAL / 2, 256>>>();
    mma_gemm_kernel<<<tgrid, 256, TC_SMEM>>>();
    reduce_kernel<<<rblocks, 256>>>(nullptr, 1, nullptr, 0);

    // stage 3: y = relu(conv(y, f1) + x)            -> d_out
    wgemm_kernel<<<wgrid, 256>>>(nullptr, 0, 1);
    wtsplit_kernel<<<KT_TOTAL / 2, 256>>>();
    mma_gemm_kernel<<<tgrid, 256, TC_SMEM>>>();
    reduce_kernel<<<rblocks, 256>>>(x, 1, out, 2);
}